// round 1
// baseline (speedup 1.0000x reference)
#include <cuda_runtime.h>
#include <math.h>

#define Bsz  4
#define Nseq 2048
#define Cdim 64
#define Hn   16
#define Dh   64
#define HID  1024
#define MTOT (Bsz*Nseq)     // 8192

// Scratch (device globals: no allocations allowed)
__device__ float g_q[(size_t)Bsz*Hn*Nseq*Dh];
__device__ float g_k[(size_t)Bsz*Hn*Nseq*Dh];
__device__ float g_v[(size_t)Bsz*Hn*Nseq*Dh];
__device__ float g_ctx[(size_t)MTOT*HID];

// ---------------------------------------------------------------------------
// Kernel 1: QKV projection. Y = X @ W + b, scatter into Q/K/V [B,H,N,D].
// X: [8192,64], W: [64,3072]. Tile 64x64, 256 threads, 4x4 per thread.
// ---------------------------------------------------------------------------
__global__ __launch_bounds__(256) void qkv_kernel(
    const float* __restrict__ X, const float* __restrict__ W,
    const float* __restrict__ bias)
{
    __shared__ float Xs[64*64];
    __shared__ float Ws[64*64];
    const int m0 = blockIdx.y * 64;
    const int j0 = blockIdx.x * 64;
    const int tid = threadIdx.x;
    const int tx = tid & 15, ty = tid >> 4;

    for (int i = tid; i < 64*16; i += 256) {
        int r = i >> 4, c = i & 15;
        ((float4*)Xs)[r*16 + c] = ((const float4*)(X + (size_t)(m0 + r)*Cdim))[c];
        ((float4*)Ws)[r*16 + c] = ((const float4*)(W + (size_t)r*(3*HID) + j0))[c];
    }
    __syncthreads();

    float acc[4][4] = {};
    #pragma unroll
    for (int k = 0; k < 64; k++) {
        float a[4];
        #pragma unroll
        for (int ii = 0; ii < 4; ii++) a[ii] = Xs[(4*ty+ii)*64 + k];
        float4 bv = ((float4*)Ws)[k*16 + tx];
        #pragma unroll
        for (int ii = 0; ii < 4; ii++) {
            acc[ii][0] += a[ii]*bv.x; acc[ii][1] += a[ii]*bv.y;
            acc[ii][2] += a[ii]*bv.z; acc[ii][3] += a[ii]*bv.w;
        }
    }

    // whole 64-col tile maps to one (three, head) pair
    const int three = j0 / HID;
    const int h     = (j0 >> 6) & 15;
    float* dst_base = (three == 0) ? g_q : (three == 1) ? g_k : g_v;
    float4 b4 = ((const float4*)(bias + j0))[tx];

    #pragma unroll
    for (int ii = 0; ii < 4; ii++) {
        int m = m0 + 4*ty + ii;
        int bb = m >> 11;          // / 2048
        int n  = m & 2047;
        float4 o;
        o.x = acc[ii][0] + b4.x; o.y = acc[ii][1] + b4.y;
        o.z = acc[ii][2] + b4.z; o.w = acc[ii][3] + b4.w;
        *(float4*)(dst_base + (((size_t)(bb*Hn + h))*Nseq + n)*Dh + 4*tx) = o;
    }
}

// ---------------------------------------------------------------------------
// Kernel 2: flash attention. Block = (q-tile of 64) x (b*H). 256 threads.
// Qs[64][64] (pre-scaled), Ks[64][65] (padded; reused for P), Vs[64][64].
// Online softmax, 4x4 register blocking for both S = Q K^T and O += P V.
// ---------------------------------------------------------------------------
extern __shared__ float sm_attn[];

__global__ __launch_bounds__(256) void attn_kernel()
{
    float* Qs = sm_attn;          // 4096
    float* Ks = sm_attn + 4096;   // 64*65 = 4160 (also holds P)
    float* Vs = sm_attn + 8256;   // 4096   -> total 12352 floats = 49408 B

    const int bh = blockIdx.y;          // b*H + h
    const int q0 = blockIdx.x * 64;
    const float* Qg = g_q + ((size_t)bh*Nseq + q0)*Dh;
    const float* Kg = g_k + (size_t)bh*Nseq*Dh;
    const float* Vg = g_v + (size_t)bh*Nseq*Dh;

    const int tid = threadIdx.x;
    const int tx = tid & 15, ty = tid >> 4;

    // load Q tile, pre-scaled by 1/sqrt(64)
    for (int i = tid; i < 1024; i += 256) {
        float4 v = ((const float4*)Qg)[i];
        v.x *= 0.125f; v.y *= 0.125f; v.z *= 0.125f; v.w *= 0.125f;
        ((float4*)Qs)[i] = v;
    }

    float M[4], L[4], O[4][4];
    #pragma unroll
    for (int ii = 0; ii < 4; ii++) {
        M[ii] = -1e30f; L[ii] = 0.f;
        #pragma unroll
        for (int jj = 0; jj < 4; jj++) O[ii][jj] = 0.f;
    }

    for (int jt = 0; jt < Nseq/64; jt++) {
        __syncthreads();   // prior PV reads done (also fences Q load on jt=0)
        const float* Kt = Kg + (size_t)jt*64*Dh;
        const float* Vt = Vg + (size_t)jt*64*Dh;
        for (int i = tid; i < 1024; i += 256) {
            int r = i >> 4, c = i & 15;
            float4 kv = ((const float4*)Kt)[i];
            float* kd = Ks + r*65 + c*4;
            kd[0] = kv.x; kd[1] = kv.y; kd[2] = kv.z; kd[3] = kv.w;
            ((float4*)Vs)[i] = ((const float4*)Vt)[i];
        }
        __syncthreads();

        // S = Q K^T  (64x64 tile, 4x4 per thread)
        float s[4][4] = {};
        #pragma unroll
        for (int k = 0; k < 64; k++) {
            float a[4], b[4];
            #pragma unroll
            for (int ii = 0; ii < 4; ii++) a[ii] = Qs[(4*ty+ii)*64 + k];
            #pragma unroll
            for (int jj = 0; jj < 4; jj++) b[jj] = Ks[(4*tx+jj)*65 + k];
            #pragma unroll
            for (int ii = 0; ii < 4; ii++)
                #pragma unroll
                for (int jj = 0; jj < 4; jj++)
                    s[ii][jj] += a[ii]*b[jj];
        }

        // online softmax (row groups = 16 tx lanes, butterfly shfl)
        #pragma unroll
        for (int ii = 0; ii < 4; ii++) {
            float rm = fmaxf(fmaxf(s[ii][0], s[ii][1]), fmaxf(s[ii][2], s[ii][3]));
            rm = fmaxf(rm, __shfl_xor_sync(0xffffffffu, rm, 1));
            rm = fmaxf(rm, __shfl_xor_sync(0xffffffffu, rm, 2));
            rm = fmaxf(rm, __shfl_xor_sync(0xffffffffu, rm, 4));
            rm = fmaxf(rm, __shfl_xor_sync(0xffffffffu, rm, 8));
            float mnew  = fmaxf(M[ii], rm);
            float alpha = __expf(M[ii] - mnew);
            M[ii] = mnew;
            float rs = 0.f;
            #pragma unroll
            for (int jj = 0; jj < 4; jj++) {
                s[ii][jj] = __expf(s[ii][jj] - mnew);
                rs += s[ii][jj];
            }
            rs += __shfl_xor_sync(0xffffffffu, rs, 1);
            rs += __shfl_xor_sync(0xffffffffu, rs, 2);
            rs += __shfl_xor_sync(0xffffffffu, rs, 4);
            rs += __shfl_xor_sync(0xffffffffu, rs, 8);
            L[ii] = L[ii]*alpha + rs;
            #pragma unroll
            for (int jj = 0; jj < 4; jj++) O[ii][jj] *= alpha;
        }

        __syncthreads();   // everyone done reading Ks as K
        #pragma unroll
        for (int ii = 0; ii < 4; ii++)
            #pragma unroll
            for (int jj = 0; jj < 4; jj++)
                Ks[(4*ty+ii)*65 + (4*tx+jj)] = s[ii][jj];   // P
        __syncthreads();

        // O += P V
        #pragma unroll
        for (int k = 0; k < 64; k++) {
            float p[4];
            #pragma unroll
            for (int ii = 0; ii < 4; ii++) p[ii] = Ks[(4*ty+ii)*65 + k];
            float4 vv = ((float4*)Vs)[k*16 + tx];
            #pragma unroll
            for (int ii = 0; ii < 4; ii++) {
                O[ii][0] += p[ii]*vv.x; O[ii][1] += p[ii]*vv.y;
                O[ii][2] += p[ii]*vv.z; O[ii][3] += p[ii]*vv.w;
            }
        }
    }

    // epilogue: normalize, write ctx[b][n][h*64+d]
    const int bb = bh >> 4, h = bh & 15;
    #pragma unroll
    for (int ii = 0; ii < 4; ii++) {
        float inv = 1.f / L[ii];
        int n = q0 + 4*ty + ii;
        float4 o;
        o.x = O[ii][0]*inv; o.y = O[ii][1]*inv;
        o.z = O[ii][2]*inv; o.w = O[ii][3]*inv;
        *(float4*)(g_ctx + ((size_t)(bb*Nseq + n))*HID + h*Dh + 4*tx) = o;
    }
}

// ---------------------------------------------------------------------------
// Kernel 3: out = GELU(ctx @ Wo + bo).  ctx [8192,1024], Wo [1024,64].
// ---------------------------------------------------------------------------
__global__ __launch_bounds__(256) void out_kernel(
    const float* __restrict__ Wo, const float* __restrict__ bo,
    float* __restrict__ out)
{
    __shared__ float As[64*64];
    __shared__ float Bs[64*64];
    const int m0 = blockIdx.x * 64;
    const int tid = threadIdx.x;
    const int tx = tid & 15, ty = tid >> 4;

    float acc[4][4] = {};
    for (int kt = 0; kt < HID/64; kt++) {
        for (int i = tid; i < 64*16; i += 256) {
            int r = i >> 4, c = i & 15;
            ((float4*)As)[r*16 + c] =
                ((const float4*)(g_ctx + (size_t)(m0 + r)*HID + kt*64))[c];
            ((float4*)Bs)[r*16 + c] =
                ((const float4*)(Wo + (size_t)(kt*64 + r)*Cdim))[c];
        }
        __syncthreads();
        #pragma unroll
        for (int k = 0; k < 64; k++) {
            float a[4];
            #pragma unroll
            for (int ii = 0; ii < 4; ii++) a[ii] = As[(4*ty+ii)*64 + k];
            float4 bv = ((float4*)Bs)[k*16 + tx];
            #pragma unroll
            for (int ii = 0; ii < 4; ii++) {
                acc[ii][0] += a[ii]*bv.x; acc[ii][1] += a[ii]*bv.y;
                acc[ii][2] += a[ii]*bv.z; acc[ii][3] += a[ii]*bv.w;
            }
        }
        __syncthreads();
    }

    float4 b4 = ((const float4*)bo)[tx];
    #pragma unroll
    for (int ii = 0; ii < 4; ii++) {
        float v[4];
        v[0] = acc[ii][0] + b4.x; v[1] = acc[ii][1] + b4.y;
        v[2] = acc[ii][2] + b4.z; v[3] = acc[ii][3] + b4.w;
        #pragma unroll
        for (int jj = 0; jj < 4; jj++)
            v[jj] = 0.5f * v[jj] * (1.0f + erff(v[jj] * 0.70710678118654752f));
        float4 o; o.x = v[0]; o.y = v[1]; o.z = v[2]; o.w = v[3];
        *(float4*)(out + (size_t)(m0 + 4*ty + ii)*Cdim + 4*tx) = o;
    }
}

// ---------------------------------------------------------------------------
extern "C" void kernel_launch(void* const* d_in, const int* in_sizes, int n_in,
                              void* d_out, int out_size)
{
    const float* X  = (const float*)d_in[0];   // hidden_states [4,2048,64]
    const float* Wq = (const float*)d_in[1];   // qkv_w [64,3072]
    const float* bq = (const float*)d_in[2];   // qkv_b [3072]
    const float* Wo = (const float*)d_in[3];   // out_w [1024,64]
    const float* bo = (const float*)d_in[4];   // out_b [64]
    float* out = (float*)d_out;

    cudaFuncSetAttribute(attn_kernel,
                         cudaFuncAttributeMaxDynamicSharedMemorySize, 12352*4);

    qkv_kernel<<<dim3(48, 128), 256>>>(X, Wq, bq);
    attn_kernel<<<dim3(Nseq/64, Bsz*Hn), 256, 12352*4>>>();
    out_kernel<<<MTOT/64, 256>>>(Wo, bo, out);
}

// round 3
// speedup vs baseline: 2.8489x; 2.8489x over previous
#include <cuda_runtime.h>
#include <math.h>
#include <stdint.h>

#define Bsz  4
#define Nseq 2048
#define Cdim 64
#define Hn   16
#define Dh   64
#define HID  1024
#define MTOT (Bsz*Nseq)     // 8192

// Scratch (device globals: no allocations allowed)
__device__ float g_q[(size_t)Bsz*Hn*Nseq*Dh];
__device__ float g_k[(size_t)Bsz*Hn*Nseq*Dh];
__device__ float g_v[(size_t)Bsz*Hn*Nseq*Dh];
__device__ float g_ctx[(size_t)MTOT*HID];

__device__ __forceinline__ float ex2f(float x) {
    float r; asm("ex2.approx.ftz.f32 %0, %1;" : "=f"(r) : "f"(x)); return r;
}
__device__ __forceinline__ uint32_t f2tf32(float x) {
    uint32_t r; asm("cvt.rna.tf32.f32 %0, %1;" : "=r"(r) : "f"(x)); return r;
}
__device__ __forceinline__ void mma_tf32(float d[4], const uint32_t a[4],
                                         uint32_t b0, uint32_t b1) {
    asm volatile("mma.sync.aligned.m16n8k8.row.col.f32.tf32.tf32.f32 "
        "{%0,%1,%2,%3}, {%4,%5,%6,%7}, {%8,%9}, {%0,%1,%2,%3};"
        : "+f"(d[0]), "+f"(d[1]), "+f"(d[2]), "+f"(d[3])
        : "r"(a[0]), "r"(a[1]), "r"(a[2]), "r"(a[3]), "r"(b0), "r"(b1));
}

// ===========================================================================
// Kernel 1: QKV projection (fp32)
// ===========================================================================
__global__ __launch_bounds__(256) void qkv_kernel(
    const float* __restrict__ X, const float* __restrict__ W,
    const float* __restrict__ bias)
{
    __shared__ float Xs[64*64];
    __shared__ float Ws[64*64];
    const int m0 = blockIdx.y * 64;
    const int j0 = blockIdx.x * 64;
    const int tid = threadIdx.x;
    const int tx = tid & 15, ty = tid >> 4;

    for (int i = tid; i < 64*16; i += 256) {
        int r = i >> 4, c = i & 15;
        ((float4*)Xs)[r*16 + c] = ((const float4*)(X + (size_t)(m0 + r)*Cdim))[c];
        ((float4*)Ws)[r*16 + c] = ((const float4*)(W + (size_t)r*(3*HID) + j0))[c];
    }
    __syncthreads();

    float acc[4][4] = {};
    #pragma unroll
    for (int k = 0; k < 64; k++) {
        float a[4];
        #pragma unroll
        for (int ii = 0; ii < 4; ii++) a[ii] = Xs[(4*ty+ii)*64 + k];
        float4 bv = ((float4*)Ws)[k*16 + tx];
        #pragma unroll
        for (int ii = 0; ii < 4; ii++) {
            acc[ii][0] += a[ii]*bv.x; acc[ii][1] += a[ii]*bv.y;
            acc[ii][2] += a[ii]*bv.z; acc[ii][3] += a[ii]*bv.w;
        }
    }

    const int three = j0 / HID;
    const int h     = (j0 >> 6) & 15;
    float* dst_base = (three == 0) ? g_q : (three == 1) ? g_k : g_v;
    float4 b4 = ((const float4*)(bias + j0))[tx];

    #pragma unroll
    for (int ii = 0; ii < 4; ii++) {
        int m = m0 + 4*ty + ii;
        int bb = m >> 11;
        int n  = m & 2047;
        float4 o;
        o.x = acc[ii][0] + b4.x; o.y = acc[ii][1] + b4.y;
        o.z = acc[ii][2] + b4.z; o.w = acc[ii][3] + b4.w;
        *(float4*)(dst_base + (((size_t)(bb*Hn + h))*Nseq + n)*Dh + 4*tx) = o;
    }
}

// ===========================================================================
// Kernel 2: flash attention via mma.sync tf32 (m16n8k8).
// CTA: 128 q-rows x (b,h). 8 warps; warp w owns rows [16w,16w+16), all 128 kv.
// smem: K [128][68], V [128][72], Q [128][68] (tf32-converted, Q pre-scaled).
// Pads chosen so all fragment LDS patterns are bank-conflict-free.
// ===========================================================================
#define KPAD 68
#define VPAD 72
#define SM_V_OFF (128*KPAD)
#define SM_Q_OFF (SM_V_OFF + 128*VPAD)
#define SM_FLOATS (SM_Q_OFF + 128*KPAD)     // 26624 floats = 106496 B
#define QSC 0.18033688011112042f            /* 0.125 * log2(e) */

__global__ __launch_bounds__(256) void attn_mma_kernel()
{
    extern __shared__ float sm[];
    float* Ks = sm;
    float* Vs = sm + SM_V_OFF;
    float* Qs = sm + SM_Q_OFF;

    const int tid = threadIdx.x;
    const int w = tid >> 5, lane = tid & 31;
    const int q = lane & 3, g = lane >> 2;
    const int bh = blockIdx.y;
    const int q0 = blockIdx.x * 128;

    const float* Qg = g_q + ((size_t)bh*Nseq + q0)*Dh;
    const float* Kg = g_k + (size_t)bh*Nseq*Dh;
    const float* Vg = g_v + (size_t)bh*Nseq*Dh;

    // ---- stage Q tile (scaled into log2 domain, tf32) ----
    #pragma unroll
    for (int it = 0; it < 8; it++) {
        int idx = tid + it*256;
        int r = idx >> 4, c = (idx & 15) * 4;
        float4 v = ((const float4*)Qg)[idx];
        uint4 t;
        t.x = f2tf32(v.x*QSC); t.y = f2tf32(v.y*QSC);
        t.z = f2tf32(v.z*QSC); t.w = f2tf32(v.w*QSC);
        *(uint4*)&Qs[r*KPAD + c] = t;
    }
    __syncthreads();

    // ---- Q a-fragments into registers (rows rA=16w+g, rA+8) ----
    uint32_t qa[8][4];
    {
        const int rA = 16*w + g;
        #pragma unroll
        for (int s = 0; s < 8; s++) {
            qa[s][0] = __float_as_uint(Qs[rA*KPAD + 8*s + q]);
            qa[s][1] = __float_as_uint(Qs[(rA+8)*KPAD + 8*s + q]);
            qa[s][2] = __float_as_uint(Qs[rA*KPAD + 8*s + q + 4]);
            qa[s][3] = __float_as_uint(Qs[(rA+8)*KPAD + 8*s + q + 4]);
        }
    }

    float M0 = -1e30f, M1 = -1e30f, L0 = 0.f, L1 = 0.f;
    float O[8][4];
    #pragma unroll
    for (int dc = 0; dc < 8; dc++)
        #pragma unroll
        for (int j = 0; j < 4; j++) O[dc][j] = 0.f;

    for (int kt = 0; kt < 16; kt++) {
        __syncthreads();   // previous tile's smem reads complete
        const float* Kt = Kg + (size_t)kt*128*Dh;
        const float* Vt = Vg + (size_t)kt*128*Dh;
        #pragma unroll
        for (int it = 0; it < 8; it++) {
            int idx = tid + it*256;
            int r = idx >> 4, c = (idx & 15) * 4;
            float4 kv = ((const float4*)Kt)[idx];
            uint4 tk;
            tk.x = f2tf32(kv.x); tk.y = f2tf32(kv.y);
            tk.z = f2tf32(kv.z); tk.w = f2tf32(kv.w);
            *(uint4*)&Ks[r*KPAD + c] = tk;
            float4 vv = ((const float4*)Vt)[idx];
            uint4 tv;
            tv.x = f2tf32(vv.x); tv.y = f2tf32(vv.y);
            tv.z = f2tf32(vv.z); tv.w = f2tf32(vv.w);
            *(uint4*)&Vs[r*VPAD + c] = tv;
        }
        __syncthreads();

        // ---- S = Q K^T : 16 n-chunks x 8 k-steps ----
        float s[16][4];
        #pragma unroll
        for (int c = 0; c < 16; c++) {
            s[c][0] = 0.f; s[c][1] = 0.f; s[c][2] = 0.f; s[c][3] = 0.f;
            #pragma unroll
            for (int ks = 0; ks < 8; ks++) {
                uint32_t b0 = __float_as_uint(Ks[(8*c + g)*KPAD + 8*ks + q]);
                uint32_t b1 = __float_as_uint(Ks[(8*c + g)*KPAD + 8*ks + q + 4]);
                mma_tf32(s[c], qa[ks], b0, b1);
            }
        }

        // ---- online softmax (rows rA, rA+8; quad reduction) ----
        float m0 = s[0][0], m1 = s[0][2];
        #pragma unroll
        for (int c = 0; c < 16; c++) {
            m0 = fmaxf(m0, fmaxf(s[c][0], s[c][1]));
            m1 = fmaxf(m1, fmaxf(s[c][2], s[c][3]));
        }
        m0 = fmaxf(m0, __shfl_xor_sync(0xffffffffu, m0, 1));
        m0 = fmaxf(m0, __shfl_xor_sync(0xffffffffu, m0, 2));
        m1 = fmaxf(m1, __shfl_xor_sync(0xffffffffu, m1, 1));
        m1 = fmaxf(m1, __shfl_xor_sync(0xffffffffu, m1, 2));
        float mn0 = fmaxf(M0, m0), mn1 = fmaxf(M1, m1);
        float al0 = ex2f(M0 - mn0), al1 = ex2f(M1 - mn1);
        M0 = mn0; M1 = mn1;

        float p0 = 0.f, p1 = 0.f;
        #pragma unroll
        for (int c = 0; c < 16; c++) {
            float p;
            p = ex2f(s[c][0] - mn0); p0 += p; s[c][0] = __uint_as_float(f2tf32(p));
            p = ex2f(s[c][1] - mn0); p0 += p; s[c][1] = __uint_as_float(f2tf32(p));
            p = ex2f(s[c][2] - mn1); p1 += p; s[c][2] = __uint_as_float(f2tf32(p));
            p = ex2f(s[c][3] - mn1); p1 += p; s[c][3] = __uint_as_float(f2tf32(p));
        }
        p0 += __shfl_xor_sync(0xffffffffu, p0, 1);
        p0 += __shfl_xor_sync(0xffffffffu, p0, 2);
        p1 += __shfl_xor_sync(0xffffffffu, p1, 1);
        p1 += __shfl_xor_sync(0xffffffffu, p1, 2);
        L0 = L0*al0 + p0;
        L1 = L1*al1 + p1;
        #pragma unroll
        for (int dc = 0; dc < 8; dc++) {
            O[dc][0] *= al0; O[dc][1] *= al0;
            O[dc][2] *= al1; O[dc][3] *= al1;
        }

        // ---- O += P V : permute P d-frag -> a-frag via quad shuffles ----
        const int src1 = (lane & ~3) | (q >> 1);
        const int src2 = src1 + 2;
        #pragma unroll
        for (int kc = 0; kc < 16; kc++) {
            float x0 = __shfl_sync(0xffffffffu, s[kc][0], src1);
            float x1 = __shfl_sync(0xffffffffu, s[kc][1], src1);
            float x2 = __shfl_sync(0xffffffffu, s[kc][2], src1);
            float x3 = __shfl_sync(0xffffffffu, s[kc][3], src1);
            float y0 = __shfl_sync(0xffffffffu, s[kc][0], src2);
            float y1 = __shfl_sync(0xffffffffu, s[kc][1], src2);
            float y2 = __shfl_sync(0xffffffffu, s[kc][2], src2);
            float y3 = __shfl_sync(0xffffffffu, s[kc][3], src2);
            uint32_t A[4];
            A[0] = __float_as_uint((q & 1) ? x1 : x0);
            A[1] = __float_as_uint((q & 1) ? x3 : x2);
            A[2] = __float_as_uint((q & 1) ? y1 : y0);
            A[3] = __float_as_uint((q & 1) ? y3 : y2);
            #pragma unroll
            for (int dc = 0; dc < 8; dc++) {
                uint32_t b0 = __float_as_uint(Vs[(8*kc + q)*VPAD + 8*dc + g]);
                uint32_t b1 = __float_as_uint(Vs[(8*kc + q + 4)*VPAD + 8*dc + g]);
                mma_tf32(O[dc], A, b0, b1);
            }
        }
    }

    // ---- epilogue: normalize, write ctx[b][n][h*64+d] ----
    const float i0 = 1.f / L0, i1 = 1.f / L1;
    const int bb = bh >> 4, h = bh & 15;
    const int rA = q0 + 16*w + g;
    #pragma unroll
    for (int dc = 0; dc < 8; dc++) {
        float2 oa; oa.x = O[dc][0]*i0; oa.y = O[dc][1]*i0;
        float2 ob; ob.x = O[dc][2]*i1; ob.y = O[dc][3]*i1;
        *(float2*)&g_ctx[(size_t)(bb*Nseq + rA)*HID     + h*64 + 8*dc + 2*q] = oa;
        *(float2*)&g_ctx[(size_t)(bb*Nseq + rA + 8)*HID + h*64 + 8*dc + 2*q] = ob;
    }
}

// ===========================================================================
// Kernel 3: out = GELU(ctx @ Wo + bo)  (fp32)
// ===========================================================================
__global__ __launch_bounds__(256) void out_kernel(
    const float* __restrict__ Wo, const float* __restrict__ bo,
    float* __restrict__ out)
{
    __shared__ float As[64*64];
    __shared__ float Bs[64*64];
    const int m0 = blockIdx.x * 64;
    const int tid = threadIdx.x;
    const int tx = tid & 15, ty = tid >> 4;

    float acc[4][4] = {};
    for (int kt = 0; kt < HID/64; kt++) {
        for (int i = tid; i < 64*16; i += 256) {
            int r = i >> 4, c = i & 15;
            ((float4*)As)[r*16 + c] =
                ((const float4*)(g_ctx + (size_t)(m0 + r)*HID + kt*64))[c];
            ((float4*)Bs)[r*16 + c] =
                ((const float4*)(Wo + (size_t)(kt*64 + r)*Cdim))[c];
        }
        __syncthreads();
        #pragma unroll
        for (int k = 0; k < 64; k++) {
            float a[4];
            #pragma unroll
            for (int ii = 0; ii < 4; ii++) a[ii] = As[(4*ty+ii)*64 + k];
            float4 bv = ((float4*)Bs)[k*16 + tx];
            #pragma unroll
            for (int ii = 0; ii < 4; ii++) {
                acc[ii][0] += a[ii]*bv.x; acc[ii][1] += a[ii]*bv.y;
                acc[ii][2] += a[ii]*bv.z; acc[ii][3] += a[ii]*bv.w;
            }
        }
        __syncthreads();
    }

    float4 b4 = ((const float4*)bo)[tx];
    #pragma unroll
    for (int ii = 0; ii < 4; ii++) {
        float v[4];
        v[0] = acc[ii][0] + b4.x; v[1] = acc[ii][1] + b4.y;
        v[2] = acc[ii][2] + b4.z; v[3] = acc[ii][3] + b4.w;
        #pragma unroll
        for (int jj = 0; jj < 4; jj++)
            v[jj] = 0.5f * v[jj] * (1.0f + erff(v[jj] * 0.70710678118654752f));
        float4 o; o.x = v[0]; o.y = v[1]; o.z = v[2]; o.w = v[3];
        *(float4*)(out + (size_t)(m0 + 4*ty + ii)*Cdim + 4*tx) = o;
    }
}

// ===========================================================================
extern "C" void kernel_launch(void* const* d_in, const int* in_sizes, int n_in,
                              void* d_out, int out_size)
{
    const float* X  = (const float*)d_in[0];   // hidden_states [4,2048,64]
    const float* Wq = (const float*)d_in[1];   // qkv_w [64,3072]
    const float* bq = (const float*)d_in[2];   // qkv_b [3072]
    const float* Wo = (const float*)d_in[3];   // out_w [1024,64]
    const float* bo = (const float*)d_in[4];   // out_b [64]
    float* out = (float*)d_out;

    cudaFuncSetAttribute(attn_mma_kernel,
                         cudaFuncAttributeMaxDynamicSharedMemorySize,
                         SM_FLOATS * 4);

    qkv_kernel<<<dim3(48, 128), 256>>>(X, Wq, bq);
    attn_mma_kernel<<<dim3(Nseq/128, Bsz*Hn), 256, SM_FLOATS*4>>>();
    out_kernel<<<MTOT/64, 256>>>(Wo, bo, out);
}

// round 4
// speedup vs baseline: 4.9891x; 1.7512x over previous
#include <cuda_runtime.h>
#include <cuda_fp16.h>
#include <math.h>
#include <stdint.h>

#define Bsz  4
#define Nseq 2048
#define Cdim 64
#define Hn   16
#define Dh   64
#define HID  1024
#define MTOT (Bsz*Nseq)     // 8192
#define QSC 0.18033688011112042f            /* 0.125 * log2(e) */

// Scratch (device globals)
__device__ __half g_qh[(size_t)Bsz*Hn*Nseq*Dh];   // [bh][n][d], pre-scaled by QSC
__device__ __half g_kh[(size_t)Bsz*Hn*Nseq*Dh];   // [bh][n][d]
__device__ __half g_vt[(size_t)Bsz*Hn*Dh*Nseq];   // [bh][d][n]  (V transposed)
__device__ float  g_ctx[(size_t)MTOT*HID];

__device__ __forceinline__ float ex2f(float x) {
    float r; asm("ex2.approx.ftz.f32 %0, %1;" : "=f"(r) : "f"(x)); return r;
}
__device__ __forceinline__ uint32_t h2u(__half2 h) { return *(uint32_t*)&h; }

__device__ __forceinline__ void mma_f16(float d[4], const uint32_t a[4],
                                        uint32_t b0, uint32_t b1) {
    asm volatile("mma.sync.aligned.m16n8k16.row.col.f32.f16.f16.f32 "
        "{%0,%1,%2,%3}, {%4,%5,%6,%7}, {%8,%9}, {%0,%1,%2,%3};"
        : "+f"(d[0]), "+f"(d[1]), "+f"(d[2]), "+f"(d[3])
        : "r"(a[0]), "r"(a[1]), "r"(a[2]), "r"(a[3]), "r"(b0), "r"(b1));
}

// ===========================================================================
// Kernel 1: QKV projection via fp16 mma. Block: 128 rows x 64 cols, K=64.
// Writes Q (scaled, half), K (half), V (half, transposed [bh][d][n]).
// ===========================================================================
#define XPAD 72
__global__ __launch_bounds__(256) void qkv_kernel(
    const float* __restrict__ X, const float* __restrict__ W,
    const float* __restrict__ bias)
{
    __shared__ __half Xh[128*XPAD];
    __shared__ __half Wh[64*XPAD];
    const int m0 = blockIdx.y * 128;
    const int j0 = blockIdx.x * 64;
    const int tid = threadIdx.x;
    const int w = tid >> 5, lane = tid & 31;
    const int q = lane & 3, g = lane >> 2;

    // X tile [128][64] fp32 -> half
    #pragma unroll
    for (int it = 0; it < 8; it++) {
        int idx = tid + it*256;
        int r = idx >> 4, c = (idx & 15) * 4;
        float4 v = ((const float4*)(X + (size_t)m0*Cdim))[idx];
        uint2 p;
        p.x = h2u(__floats2half2_rn(v.x, v.y));
        p.y = h2u(__floats2half2_rn(v.z, v.w));
        *(uint2*)&Xh[r*XPAD + c] = p;
    }
    // W slice transposed: Wh[n][k],  W is [64][3072]
    {
        const int n = tid & 63, kb = (tid >> 6) * 16;
        float v[16];
        #pragma unroll
        for (int k = 0; k < 16; k++)
            v[k] = W[(size_t)(kb + k)*(3*HID) + j0 + n];
        #pragma unroll
        for (int k = 0; k < 16; k += 2)
            *(uint32_t*)&Wh[n*XPAD + kb + k] = h2u(__floats2half2_rn(v[k], v[k+1]));
    }
    __syncthreads();

    // a-frags: warp w owns rows 16w+g, 16w+g+8
    const int rA = 16*w + g;
    uint32_t a[4][4];
    #pragma unroll
    for (int ks = 0; ks < 4; ks++) {
        a[ks][0] = *(uint32_t*)&Xh[rA*XPAD + 16*ks + 2*q];
        a[ks][1] = *(uint32_t*)&Xh[(rA+8)*XPAD + 16*ks + 2*q];
        a[ks][2] = *(uint32_t*)&Xh[rA*XPAD + 16*ks + 8 + 2*q];
        a[ks][3] = *(uint32_t*)&Xh[(rA+8)*XPAD + 16*ks + 8 + 2*q];
    }

    const int three = j0 / HID;
    const int h     = (j0 >> 6) & 15;
    const int mA = m0 + rA;
    const int bbA = mA >> 11, nA = mA & 2047;        // row rA
    const int mB = mA + 8;
    const int bbB = mB >> 11, nB = mB & 2047;        // row rA+8

    #pragma unroll
    for (int nc = 0; nc < 8; nc++) {
        float d[4] = {0.f, 0.f, 0.f, 0.f};
        #pragma unroll
        for (int ks = 0; ks < 4; ks++) {
            uint32_t b0 = *(uint32_t*)&Wh[(8*nc + g)*XPAD + 16*ks + 2*q];
            uint32_t b1 = *(uint32_t*)&Wh[(8*nc + g)*XPAD + 16*ks + 8 + 2*q];
            mma_f16(d, a[ks], b0, b1);
        }
        const int col = 8*nc + 2*q;
        float bx = bias[j0 + col], by = bias[j0 + col + 1];
        float v0 = d[0] + bx, v1 = d[1] + by;   // row rA
        float v2 = d[2] + bx, v3 = d[3] + by;   // row rA+8
        if (three == 0) {
            v0 *= QSC; v1 *= QSC; v2 *= QSC; v3 *= QSC;
            *(uint32_t*)&g_qh[((size_t)(bbA*Hn + h)*Nseq + nA)*Dh + col] =
                h2u(__floats2half2_rn(v0, v1));
            *(uint32_t*)&g_qh[((size_t)(bbB*Hn + h)*Nseq + nB)*Dh + col] =
                h2u(__floats2half2_rn(v2, v3));
        } else if (three == 1) {
            *(uint32_t*)&g_kh[((size_t)(bbA*Hn + h)*Nseq + nA)*Dh + col] =
                h2u(__floats2half2_rn(v0, v1));
            *(uint32_t*)&g_kh[((size_t)(bbB*Hn + h)*Nseq + nB)*Dh + col] =
                h2u(__floats2half2_rn(v2, v3));
        } else {
            // transposed: g_vt[bh][d=col][n]
            size_t baseA = ((size_t)(bbA*Hn + h)*Dh);
            size_t baseB = ((size_t)(bbB*Hn + h)*Dh);
            g_vt[(baseA + col    )*Nseq + nA] = __float2half_rn(v0);
            g_vt[(baseA + col + 1)*Nseq + nA] = __float2half_rn(v1);
            g_vt[(baseB + col    )*Nseq + nB] = __float2half_rn(v2);
            g_vt[(baseB + col + 1)*Nseq + nB] = __float2half_rn(v3);
        }
    }
}

// ===========================================================================
// Kernel 2: fp16 flash attention. CTA: 128 q-rows x (b,h), 8 warps,
// warp w owns rows [16w,16w+16) x all 128 kv. No cross-warp reductions.
// smem: Ks [128][72] half (also stages Q), Vt [64][136] half.
// ===========================================================================
#define KPADH 72
#define VPADH 136
#define SM_VT_OFF (128*KPADH)                 // in halves
#define SM_HALVES (SM_VT_OFF + 64*VPADH)      // 17920 halves = 35840 B

__global__ __launch_bounds__(256) void attn_kernel()
{
    extern __shared__ __half smh[];
    __half* Ks = smh;
    __half* Vt = smh + SM_VT_OFF;

    const int tid = threadIdx.x;
    const int w = tid >> 5, lane = tid & 31;
    const int q = lane & 3, g = lane >> 2;
    const int bh = blockIdx.y;
    const int q0 = blockIdx.x * 128;

    // ---- stage Q tile into Ks, extract a-frags ----
    {
        const __half* Qg = g_qh + ((size_t)bh*Nseq + q0)*Dh;
        #pragma unroll
        for (int it = 0; it < 4; it++) {
            int idx = tid + it*256;
            int r = idx >> 3, c = (idx & 7) * 8;
            *(uint4*)&Ks[r*KPADH + c] = ((const uint4*)Qg)[idx];
        }
    }
    __syncthreads();
    const int rA = 16*w + g;
    uint32_t qa[4][4];
    #pragma unroll
    for (int ks = 0; ks < 4; ks++) {
        qa[ks][0] = *(uint32_t*)&Ks[rA*KPADH + 16*ks + 2*q];
        qa[ks][1] = *(uint32_t*)&Ks[(rA+8)*KPADH + 16*ks + 2*q];
        qa[ks][2] = *(uint32_t*)&Ks[rA*KPADH + 16*ks + 8 + 2*q];
        qa[ks][3] = *(uint32_t*)&Ks[(rA+8)*KPADH + 16*ks + 8 + 2*q];
    }
    __syncthreads();

    const __half* Kg  = g_kh + (size_t)bh*Nseq*Dh;
    const __half* Vtg = g_vt + (size_t)bh*Dh*Nseq;

    float M0 = -1e30f, M1 = -1e30f, L0 = 0.f, L1 = 0.f;
    float O[8][4];
    #pragma unroll
    for (int dc = 0; dc < 8; dc++)
        #pragma unroll
        for (int j = 0; j < 4; j++) O[dc][j] = 0.f;

    for (int kt = 0; kt < 16; kt++) {
        // K tile [128][64] halves
        const __half* Kt = Kg + (size_t)kt*128*Dh;
        #pragma unroll
        for (int it = 0; it < 4; it++) {
            int idx = tid + it*256;
            int r = idx >> 3, c = (idx & 7) * 8;
            *(uint4*)&Ks[r*KPADH + c] = ((const uint4*)Kt)[idx];
        }
        // V^T tile [64][128] halves
        #pragma unroll
        for (int it = 0; it < 4; it++) {
            int idx = tid + it*256;
            int d = idx >> 4, c = (idx & 15) * 8;
            *(uint4*)&Vt[d*VPADH + c] =
                *(const uint4*)&Vtg[(size_t)d*Nseq + kt*128 + c];
        }
        __syncthreads();

        // ---- S = Q K^T : 16 n-chunks x 4 k-steps ----
        float s[16][4];
        #pragma unroll
        for (int c = 0; c < 16; c++) {
            s[c][0] = 0.f; s[c][1] = 0.f; s[c][2] = 0.f; s[c][3] = 0.f;
            #pragma unroll
            for (int ks = 0; ks < 4; ks++) {
                uint32_t b0 = *(uint32_t*)&Ks[(8*c + g)*KPADH + 16*ks + 2*q];
                uint32_t b1 = *(uint32_t*)&Ks[(8*c + g)*KPADH + 16*ks + 8 + 2*q];
                mma_f16(s[c], qa[ks], b0, b1);
            }
        }

        // ---- online softmax (rows rA, rA+8; quad reduction over q lanes) ----
        float m0 = s[0][0], m1 = s[0][2];
        #pragma unroll
        for (int c = 0; c < 16; c++) {
            m0 = fmaxf(m0, fmaxf(s[c][0], s[c][1]));
            m1 = fmaxf(m1, fmaxf(s[c][2], s[c][3]));
        }
        m0 = fmaxf(m0, __shfl_xor_sync(0xffffffffu, m0, 1));
        m0 = fmaxf(m0, __shfl_xor_sync(0xffffffffu, m0, 2));
        m1 = fmaxf(m1, __shfl_xor_sync(0xffffffffu, m1, 1));
        m1 = fmaxf(m1, __shfl_xor_sync(0xffffffffu, m1, 2));
        float mn0 = fmaxf(M0, m0), mn1 = fmaxf(M1, m1);
        float al0 = ex2f(M0 - mn0), al1 = ex2f(M1 - mn1);
        M0 = mn0; M1 = mn1;

        float p0 = 0.f, p1 = 0.f;
        #pragma unroll
        for (int c = 0; c < 16; c++) {
            s[c][0] = ex2f(s[c][0] - mn0); p0 += s[c][0];
            s[c][1] = ex2f(s[c][1] - mn0); p0 += s[c][1];
            s[c][2] = ex2f(s[c][2] - mn1); p1 += s[c][2];
            s[c][3] = ex2f(s[c][3] - mn1); p1 += s[c][3];
        }
        p0 += __shfl_xor_sync(0xffffffffu, p0, 1);
        p0 += __shfl_xor_sync(0xffffffffu, p0, 2);
        p1 += __shfl_xor_sync(0xffffffffu, p1, 1);
        p1 += __shfl_xor_sync(0xffffffffu, p1, 2);
        L0 = L0*al0 + p0;
        L1 = L1*al1 + p1;
        #pragma unroll
        for (int dc = 0; dc < 8; dc++) {
            O[dc][0] *= al0; O[dc][1] *= al0;
            O[dc][2] *= al1; O[dc][3] *= al1;
        }

        // ---- P (C-frag) -> fp16 A-frag directly: no shuffles ----
        uint32_t pa[8][4];
        #pragma unroll
        for (int kc = 0; kc < 8; kc++) {
            pa[kc][0] = h2u(__floats2half2_rn(s[2*kc][0],   s[2*kc][1]));
            pa[kc][1] = h2u(__floats2half2_rn(s[2*kc][2],   s[2*kc][3]));
            pa[kc][2] = h2u(__floats2half2_rn(s[2*kc+1][0], s[2*kc+1][1]));
            pa[kc][3] = h2u(__floats2half2_rn(s[2*kc+1][2], s[2*kc+1][3]));
        }

        // ---- O += P V : 8 d-chunks x 8 k-chunks ----
        #pragma unroll
        for (int dc = 0; dc < 8; dc++) {
            #pragma unroll
            for (int kc = 0; kc < 8; kc++) {
                uint32_t b0 = *(uint32_t*)&Vt[(8*dc + g)*VPADH + 16*kc + 2*q];
                uint32_t b1 = *(uint32_t*)&Vt[(8*dc + g)*VPADH + 16*kc + 8 + 2*q];
                mma_f16(O[dc], pa[kc], b0, b1);
            }
        }
        __syncthreads();
    }

    // ---- epilogue: normalize, write ctx[b][n][h*64+d] (fp32) ----
    const float i0 = 1.f / L0, i1 = 1.f / L1;
    const int bb = bh >> 4, h = bh & 15;
    const int r0 = q0 + rA;
    #pragma unroll
    for (int dc = 0; dc < 8; dc++) {
        float2 oa; oa.x = O[dc][0]*i0; oa.y = O[dc][1]*i0;
        float2 ob; ob.x = O[dc][2]*i1; ob.y = O[dc][3]*i1;
        *(float2*)&g_ctx[(size_t)(bb*Nseq + r0)*HID     + h*64 + 8*dc + 2*q] = oa;
        *(float2*)&g_ctx[(size_t)(bb*Nseq + r0 + 8)*HID + h*64 + 8*dc + 2*q] = ob;
    }
}

// ===========================================================================
// Kernel 3: out = GELU(ctx @ Wo + bo)  (fp32)
// ===========================================================================
__global__ __launch_bounds__(256) void out_kernel(
    const float* __restrict__ Wo, const float* __restrict__ bo,
    float* __restrict__ out)
{
    __shared__ float As[64*64];
    __shared__ float Bs[64*64];
    const int m0 = blockIdx.x * 64;
    const int tid = threadIdx.x;
    const int tx = tid & 15, ty = tid >> 4;

    float acc[4][4] = {};
    for (int kt = 0; kt < HID/64; kt++) {
        for (int i = tid; i < 64*16; i += 256) {
            int r = i >> 4, c = i & 15;
            ((float4*)As)[r*16 + c] =
                ((const float4*)(g_ctx + (size_t)(m0 + r)*HID + kt*64))[c];
            ((float4*)Bs)[r*16 + c] =
                ((const float4*)(Wo + (size_t)(kt*64 + r)*Cdim))[c];
        }
        __syncthreads();
        #pragma unroll
        for (int k = 0; k < 64; k++) {
            float a[4];
            #pragma unroll
            for (int ii = 0; ii < 4; ii++) a[ii] = As[(4*ty+ii)*64 + k];
            float4 bv = ((float4*)Bs)[k*16 + tx];
            #pragma unroll
            for (int ii = 0; ii < 4; ii++) {
                acc[ii][0] += a[ii]*bv.x; acc[ii][1] += a[ii]*bv.y;
                acc[ii][2] += a[ii]*bv.z; acc[ii][3] += a[ii]*bv.w;
            }
        }
        __syncthreads();
    }

    float4 b4 = ((const float4*)bo)[tx];
    #pragma unroll
    for (int ii = 0; ii < 4; ii++) {
        float v[4];
        v[0] = acc[ii][0] + b4.x; v[1] = acc[ii][1] + b4.y;
        v[2] = acc[ii][2] + b4.z; v[3] = acc[ii][3] + b4.w;
        #pragma unroll
        for (int jj = 0; jj < 4; jj++)
            v[jj] = 0.5f * v[jj] * (1.0f + erff(v[jj] * 0.70710678118654752f));
        float4 o; o.x = v[0]; o.y = v[1]; o.z = v[2]; o.w = v[3];
        *(float4*)(out + (size_t)(m0 + 4*ty + ii)*Cdim + 4*tx) = o;
    }
}

// ===========================================================================
extern "C" void kernel_launch(void* const* d_in, const int* in_sizes, int n_in,
                              void* d_out, int out_size)
{
    const float* X  = (const float*)d_in[0];   // hidden_states [4,2048,64]
    const float* Wq = (const float*)d_in[1];   // qkv_w [64,3072]
    const float* bq = (const float*)d_in[2];   // qkv_b [3072]
    const float* Wo = (const float*)d_in[3];   // out_w [1024,64]
    const float* bo = (const float*)d_in[4];   // out_b [64]
    float* out = (float*)d_out;

    cudaFuncSetAttribute(attn_kernel,
                         cudaFuncAttributeMaxDynamicSharedMemorySize,
                         SM_HALVES * 2);

    qkv_kernel<<<dim3(48, 64), 256>>>(X, Wq, bq);
    attn_kernel<<<dim3(Nseq/128, Bsz*Hn), 256, SM_HALVES*2>>>();
    out_kernel<<<MTOT/64, 256>>>(Wo, bo, out);
}

// round 5
// speedup vs baseline: 6.4178x; 1.2864x over previous
#include <cuda_runtime.h>
#include <cuda_fp16.h>
#include <math.h>
#include <stdint.h>

#define Bsz  4
#define Nseq 2048
#define Cdim 64
#define Hn   16
#define Dh   64
#define HID  1024
#define MTOT (Bsz*Nseq)     // 8192
#define QSC 0.18033688011112042f            /* 0.125 * log2(e) */

// Scratch (device globals)
__device__ __half g_qh[(size_t)Bsz*Hn*Nseq*Dh];   // [bh][n][d], pre-scaled
__device__ __half g_kh[(size_t)Bsz*Hn*Nseq*Dh];   // [bh][n][d]
__device__ __half g_vt[(size_t)Bsz*Hn*Dh*Nseq];   // [bh][d][n]  (V transposed)
__device__ __half g_ctxh[(size_t)MTOT*HID];       // [n][1024] half
__device__ __half g_woh[(size_t)Cdim*HID];        // [n=64][k=1024] (Wo^T, half)

__device__ __forceinline__ float ex2f(float x) {
    float r; asm("ex2.approx.ftz.f32 %0, %1;" : "=f"(r) : "f"(x)); return r;
}
__device__ __forceinline__ uint32_t ex2h2(uint32_t x) {
    uint32_t r; asm("ex2.approx.f16x2 %0, %1;" : "=r"(r) : "r"(x)); return r;
}
__device__ __forceinline__ uint32_t h2u(__half2 h) { return *(uint32_t*)&h; }

__device__ __forceinline__ void mma_f16(float d[4], const uint32_t a[4],
                                        uint32_t b0, uint32_t b1) {
    asm volatile("mma.sync.aligned.m16n8k16.row.col.f32.f16.f16.f32 "
        "{%0,%1,%2,%3}, {%4,%5,%6,%7}, {%8,%9}, {%0,%1,%2,%3};"
        : "+f"(d[0]), "+f"(d[1]), "+f"(d[2]), "+f"(d[3])
        : "r"(a[0]), "r"(a[1]), "r"(a[2]), "r"(a[3]), "r"(b0), "r"(b1));
}
__device__ __forceinline__ void cp16(uint32_t dst, const void* src) {
    asm volatile("cp.async.cg.shared.global [%0], [%1], 16;" :: "r"(dst), "l"(src));
}
__device__ __forceinline__ void cp_commit() {
    asm volatile("cp.async.commit_group;");
}
__device__ __forceinline__ void cp_wait0() {
    asm volatile("cp.async.wait_group 0;" ::: "memory");
}

// ===========================================================================
// Kernel 1: QKV projection via fp16 mma.
// ===========================================================================
#define XPAD 72
#define VTP 136
__global__ __launch_bounds__(256) void qkv_kernel(
    const float* __restrict__ X, const float* __restrict__ W,
    const float* __restrict__ bias)
{
    __shared__ __half Xh[128*XPAD];
    __shared__ __half Wh[64*XPAD];
    __shared__ __half VTs[64*VTP];
    const int m0 = blockIdx.y * 128;
    const int j0 = blockIdx.x * 64;
    const int tid = threadIdx.x;
    const int w = tid >> 5, lane = tid & 31;
    const int q = lane & 3, g = lane >> 2;

    // X tile [128][64] fp32 -> half
    #pragma unroll
    for (int it = 0; it < 8; it++) {
        int idx = tid + it*256;
        int r = idx >> 4, c = (idx & 15) * 4;
        float4 v = ((const float4*)(X + (size_t)m0*Cdim))[idx];
        uint2 p;
        p.x = h2u(__floats2half2_rn(v.x, v.y));
        p.y = h2u(__floats2half2_rn(v.z, v.w));
        *(uint2*)&Xh[r*XPAD + c] = p;
    }
    // W slice transposed: Wh[n][k]
    {
        const int n = tid & 63, kb = (tid >> 6) * 16;
        float v[16];
        #pragma unroll
        for (int k = 0; k < 16; k++)
            v[k] = W[(size_t)(kb + k)*(3*HID) + j0 + n];
        #pragma unroll
        for (int k = 0; k < 16; k += 2)
            *(uint32_t*)&Wh[n*XPAD + kb + k] = h2u(__floats2half2_rn(v[k], v[k+1]));
    }
    __syncthreads();

    const int rA = 16*w + g;
    uint32_t a[4][4];
    #pragma unroll
    for (int ks = 0; ks < 4; ks++) {
        a[ks][0] = *(uint32_t*)&Xh[rA*XPAD + 16*ks + 2*q];
        a[ks][1] = *(uint32_t*)&Xh[(rA+8)*XPAD + 16*ks + 2*q];
        a[ks][2] = *(uint32_t*)&Xh[rA*XPAD + 16*ks + 8 + 2*q];
        a[ks][3] = *(uint32_t*)&Xh[(rA+8)*XPAD + 16*ks + 8 + 2*q];
    }

    const int three = j0 / HID;          // uniform per block
    const int h     = (j0 >> 6) & 15;
    const int bb = m0 >> 11, n0 = m0 & 2047;
    const int nA = n0 + rA, nB = n0 + rA + 8;

    #pragma unroll
    for (int nc = 0; nc < 8; nc++) {
        float d[4] = {0.f, 0.f, 0.f, 0.f};
        #pragma unroll
        for (int ks = 0; ks < 4; ks++) {
            uint32_t b0 = *(uint32_t*)&Wh[(8*nc + g)*XPAD + 16*ks + 2*q];
            uint32_t b1 = *(uint32_t*)&Wh[(8*nc + g)*XPAD + 16*ks + 8 + 2*q];
            mma_f16(d, a[ks], b0, b1);
        }
        const int col = 8*nc + 2*q;
        float bx = bias[j0 + col], by = bias[j0 + col + 1];
        float v0 = d[0] + bx, v1 = d[1] + by;   // row rA
        float v2 = d[2] + bx, v3 = d[3] + by;   // row rA+8
        if (three == 0) {
            v0 *= QSC; v1 *= QSC; v2 *= QSC; v3 *= QSC;
            *(uint32_t*)&g_qh[((size_t)(bb*Hn + h)*Nseq + nA)*Dh + col] =
                h2u(__floats2half2_rn(v0, v1));
            *(uint32_t*)&g_qh[((size_t)(bb*Hn + h)*Nseq + nB)*Dh + col] =
                h2u(__floats2half2_rn(v2, v3));
        } else if (three == 1) {
            *(uint32_t*)&g_kh[((size_t)(bb*Hn + h)*Nseq + nA)*Dh + col] =
                h2u(__floats2half2_rn(v0, v1));
            *(uint32_t*)&g_kh[((size_t)(bb*Hn + h)*Nseq + nB)*Dh + col] =
                h2u(__floats2half2_rn(v2, v3));
        } else {
            // stage transposed in smem: VTs[d][n_local]
            VTs[(col    )*VTP + rA]     = __float2half_rn(v0);
            VTs[(col + 1)*VTP + rA]     = __float2half_rn(v1);
            VTs[(col    )*VTP + rA + 8] = __float2half_rn(v2);
            VTs[(col + 1)*VTP + rA + 8] = __float2half_rn(v3);
        }
    }

    if (three == 2) {      // uniform branch: coalesced transposed writeout
        __syncthreads();
        size_t base = (size_t)(bb*Hn + h)*Dh;
        #pragma unroll
        for (int it = 0; it < 4; it++) {
            int idx = tid + it*256;          // 0..1023
            int d = idx >> 4, c = (idx & 15) * 8;
            *(uint4*)&g_vt[(base + d)*Nseq + n0 + c] = *(uint4*)&VTs[d*VTP + c];
        }
    }
}

// ===========================================================================
// Kernel 2: fp16 flash attention, cp.async double-buffered, ones-row L trick.
// CTA: 128 q-rows x (b,h), 8 warps, warp w owns rows [16w,16w+16) x 128 kv.
// smem per buffer: Ks [128][72], Vt [72][136] (rows 64..71: ones row + zeros)
// ===========================================================================
#define KPADH 72
#define VPADH 136
#define KS_HALVES (128*KPADH)                 // 9216
#define VT_HALVES (72*VPADH)                  // 9792
#define BUF_HALVES (KS_HALVES + VT_HALVES)    // 19008
#define SM_ATTN_BYTES (2*BUF_HALVES*2)        // 76032 B

__global__ __launch_bounds__(256) void attn_kernel()
{
    extern __shared__ __half smh[];
    const uint32_t smbase = (uint32_t)__cvta_generic_to_shared(smh);

    const int tid = threadIdx.x;
    const int w = tid >> 5, lane = tid & 31;
    const int q = lane & 3, g = lane >> 4 ? 0 : 0;  // placeholder (replaced below)
    const int gg = lane >> 2;
    const int bh = blockIdx.y;
    const int q0 = blockIdx.x * 128;

    const __half* Kg  = g_kh + (size_t)bh*Nseq*Dh;
    const __half* Vtg = g_vt + (size_t)bh*Dh*Nseq;

    // ---- stage Q tile (buf0 Ks area), extract a-frags ----
    {
        const __half* Qg = g_qh + ((size_t)bh*Nseq + q0)*Dh;
        #pragma unroll
        for (int it = 0; it < 4; it++) {
            int idx = tid + it*256;
            int r = idx >> 3, c = (idx & 7) * 8;
            *(uint4*)&smh[r*KPADH + c] = ((const uint4*)Qg)[idx];
        }
    }
    __syncthreads();
    const int rA = 16*w + gg;
    uint32_t qa[4][4];
    #pragma unroll
    for (int ks = 0; ks < 4; ks++) {
        qa[ks][0] = *(uint32_t*)&smh[rA*KPADH + 16*ks + 2*q];
        qa[ks][1] = *(uint32_t*)&smh[(rA+8)*KPADH + 16*ks + 2*q];
        qa[ks][2] = *(uint32_t*)&smh[rA*KPADH + 16*ks + 8 + 2*q];
        qa[ks][3] = *(uint32_t*)&smh[(rA+8)*KPADH + 16*ks + 8 + 2*q];
    }
    // ---- init ones/zero rows (rows 64..71 of both V buffers) ----
    for (int i = tid; i < 8*VPADH; i += 256) {
        int rr = i / VPADH, cc = i % VPADH;
        __half val = (rr == 0) ? __float2half(1.f) : __float2half(0.f);
        smh[KS_HALVES + (64+rr)*VPADH + cc] = val;
        smh[BUF_HALVES + KS_HALVES + (64+rr)*VPADH + cc] = val;
    }
    __syncthreads();

    // ---- prologue: issue tile 0 into buf 0 ----
    {
        uint32_t ksb = smbase;
        uint32_t vtb = smbase + KS_HALVES*2;
        #pragma unroll
        for (int it = 0; it < 4; it++) {
            int idx = tid + it*256;
            int r = idx >> 3, c = (idx & 7) * 8;
            cp16(ksb + (r*KPADH + c)*2, Kg + idx*8);
        }
        #pragma unroll
        for (int it = 0; it < 4; it++) {
            int idx = tid + it*256;
            int d = idx >> 4, c = (idx & 15) * 8;
            cp16(vtb + (d*VPADH + c)*2, Vtg + (size_t)d*Nseq + c);
        }
        cp_commit();
    }

    float M0 = -1e30f, M1 = -1e30f;
    float O[8][4], Lacc[4];
    #pragma unroll
    for (int dc = 0; dc < 8; dc++)
        #pragma unroll
        for (int j = 0; j < 4; j++) O[dc][j] = 0.f;
    Lacc[0] = Lacc[1] = Lacc[2] = Lacc[3] = 0.f;

    for (int kt = 0; kt < 16; kt++) {
        cp_wait0();
        __syncthreads();
        const int buf = kt & 1;

        // issue next tile into other buffer (overlaps with compute below)
        if (kt < 15) {
            const int nb = buf ^ 1;
            uint32_t ksb = smbase + (nb*BUF_HALVES)*2;
            uint32_t vtb = ksb + KS_HALVES*2;
            const __half* Kt = Kg + (size_t)(kt+1)*128*Dh;
            const __half* Vs = Vtg + (kt+1)*128;
            #pragma unroll
            for (int it = 0; it < 4; it++) {
                int idx = tid + it*256;
                int r = idx >> 3, c = (idx & 7) * 8;
                cp16(ksb + (r*KPADH + c)*2, Kt + idx*8);
            }
            #pragma unroll
            for (int it = 0; it < 4; it++) {
                int idx = tid + it*256;
                int d = idx >> 4, c = (idx & 15) * 8;
                cp16(vtb + (d*VPADH + c)*2, Vs + (size_t)d*Nseq + c);
            }
            cp_commit();
        }

        const __half* Ks = smh + buf*BUF_HALVES;
        const __half* Vt = Ks + KS_HALVES;

        // ---- S = Q K^T : 16 n-chunks x 4 k-steps ----
        float s[16][4];
        #pragma unroll
        for (int c = 0; c < 16; c++) {
            s[c][0] = 0.f; s[c][1] = 0.f; s[c][2] = 0.f; s[c][3] = 0.f;
            #pragma unroll
            for (int ks = 0; ks < 4; ks++) {
                uint32_t b0 = *(uint32_t*)&Ks[(8*c + gg)*KPADH + 16*ks + 2*q];
                uint32_t b1 = *(uint32_t*)&Ks[(8*c + gg)*KPADH + 16*ks + 8 + 2*q];
                mma_f16(s[c], qa[ks], b0, b1);
            }
        }

        // ---- row max (quad reduction), rescale factors ----
        float m0 = s[0][0], m1 = s[0][2];
        #pragma unroll
        for (int c = 0; c < 16; c++) {
            m0 = fmaxf(m0, fmaxf(s[c][0], s[c][1]));
            m1 = fmaxf(m1, fmaxf(s[c][2], s[c][3]));
        }
        m0 = fmaxf(m0, __shfl_xor_sync(0xffffffffu, m0, 1));
        m0 = fmaxf(m0, __shfl_xor_sync(0xffffffffu, m0, 2));
        m1 = fmaxf(m1, __shfl_xor_sync(0xffffffffu, m1, 1));
        m1 = fmaxf(m1, __shfl_xor_sync(0xffffffffu, m1, 2));
        float mn0 = fmaxf(M0, m0), mn1 = fmaxf(M1, m1);
        float al0 = ex2f(M0 - mn0), al1 = ex2f(M1 - mn1);
        M0 = mn0; M1 = mn1;

        #pragma unroll
        for (int dc = 0; dc < 8; dc++) {
            O[dc][0] *= al0; O[dc][1] *= al0;
            O[dc][2] *= al1; O[dc][3] *= al1;
        }
        Lacc[0] *= al0; Lacc[1] *= al0; Lacc[2] *= al1; Lacc[3] *= al1;

        // ---- P = exp2(s - m) directly in f16x2 (A-fragment layout) ----
        uint32_t pa[8][4];
        #pragma unroll
        for (int kc = 0; kc < 8; kc++) {
            pa[kc][0] = ex2h2(h2u(__floats2half2_rn(s[2*kc][0]-mn0,   s[2*kc][1]-mn0)));
            pa[kc][1] = ex2h2(h2u(__floats2half2_rn(s[2*kc][2]-mn1,   s[2*kc][3]-mn1)));
            pa[kc][2] = ex2h2(h2u(__floats2half2_rn(s[2*kc+1][0]-mn0, s[2*kc+1][1]-mn0)));
            pa[kc][3] = ex2h2(h2u(__floats2half2_rn(s[2*kc+1][2]-mn1, s[2*kc+1][3]-mn1)));
        }

        // ---- O += P V (dc 0..7) and L += P @ ones (dc 8) ----
        #pragma unroll
        for (int kc = 0; kc < 8; kc++) {
            #pragma unroll
            for (int dc = 0; dc < 8; dc++) {
                uint32_t b0 = *(uint32_t*)&Vt[(8*dc + gg)*VPADH + 16*kc + 2*q];
                uint32_t b1 = *(uint32_t*)&Vt[(8*dc + gg)*VPADH + 16*kc + 8 + 2*q];
                mma_f16(O[dc], pa[kc], b0, b1);
            }
            uint32_t b0 = *(uint32_t*)&Vt[(64 + gg)*VPADH + 16*kc + 2*q];
            uint32_t b1 = *(uint32_t*)&Vt[(64 + gg)*VPADH + 16*kc + 8 + 2*q];
            mma_f16(Lacc, pa[kc], b0, b1);
        }
        __syncthreads();   // all reads of buf done before next-next overwrite
    }

    // ---- L lives in q==0 lanes' Lacc[0]/Lacc[2]; broadcast within quad ----
    const int srcl = lane & ~3;
    float Ls0 = __shfl_sync(0xffffffffu, Lacc[0], srcl);
    float Ls1 = __shfl_sync(0xffffffffu, Lacc[2], srcl);
    const float i0 = 1.f / Ls0, i1 = 1.f / Ls1;

    const int bb = bh >> 4, h = bh & 15;
    const int r0 = q0 + rA;
    #pragma unroll
    for (int dc = 0; dc < 8; dc++) {
        uint32_t pa0 = h2u(__floats2half2_rn(O[dc][0]*i0, O[dc][1]*i0));
        uint32_t pb0 = h2u(__floats2half2_rn(O[dc][2]*i1, O[dc][3]*i1));
        *(uint32_t*)&g_ctxh[(size_t)(bb*Nseq + r0)*HID     + h*64 + 8*dc + 2*q] = pa0;
        *(uint32_t*)&g_ctxh[(size_t)(bb*Nseq + r0 + 8)*HID + h*64 + 8*dc + 2*q] = pb0;
    }
}

// ===========================================================================
// Kernel 3a: convert Wo -> half transposed g_woh[n][k]
// ===========================================================================
__global__ void wconv_kernel(const float* __restrict__ Wo) {
    int idx = blockIdx.x * 1024 + threadIdx.x;   // 65536 total
    int n = idx >> 10, k = idx & 1023;
    g_woh[idx] = __float2half_rn(Wo[(size_t)k*Cdim + n]);
}

// ===========================================================================
// Kernel 3b: out = GELU(ctx @ Wo + bo) via fp16 mma.
// CTA: 64 rows, 128 threads (4 warps x 16 rows). K=1024 in 16 tiles of 64.
// ===========================================================================
#define OPAD 72
__global__ __launch_bounds__(128) void out_kernel(
    const float* __restrict__ bo, float* __restrict__ out)
{
    __shared__ __half As[64*OPAD];
    __shared__ __half Bs[64*OPAD];
    const int m0 = blockIdx.x * 64;
    const int tid = threadIdx.x;
    const int w = tid >> 5, lane = tid & 31;
    const int q = lane & 3, g = lane >> 2;
    const int rA = 16*w + g;

    float acc[8][4];
    #pragma unroll
    for (int nc = 0; nc < 8; nc++)
        #pragma unroll
        for (int j = 0; j < 4; j++) acc[nc][j] = 0.f;

    for (int kt = 0; kt < 16; kt++) {
        #pragma unroll
        for (int it = 0; it < 4; it++) {
            int idx = tid + it*128;
            int r = idx >> 3, c = (idx & 7) * 8;
            *(uint4*)&As[r*OPAD + c] =
                *(const uint4*)&g_ctxh[(size_t)(m0 + r)*HID + kt*64 + c];
            *(uint4*)&Bs[r*OPAD + c] =
                *(const uint4*)&g_woh[(size_t)r*HID + kt*64 + c];
        }
        __syncthreads();

        uint32_t a[4][4];
        #pragma unroll
        for (int ks = 0; ks < 4; ks++) {
            a[ks][0] = *(uint32_t*)&As[rA*OPAD + 16*ks + 2*q];
            a[ks][1] = *(uint32_t*)&As[(rA+8)*OPAD + 16*ks + 2*q];
            a[ks][2] = *(uint32_t*)&As[rA*OPAD + 16*ks + 8 + 2*q];
            a[ks][3] = *(uint32_t*)&As[(rA+8)*OPAD + 16*ks + 8 + 2*q];
        }
        #pragma unroll
        for (int nc = 0; nc < 8; nc++) {
            #pragma unroll
            for (int ks = 0; ks < 4; ks++) {
                uint32_t b0 = *(uint32_t*)&Bs[(8*nc + g)*OPAD + 16*ks + 2*q];
                uint32_t b1 = *(uint32_t*)&Bs[(8*nc + g)*OPAD + 16*ks + 8 + 2*q];
                mma_f16(acc[nc], a[ks], b0, b1);
            }
        }
        __syncthreads();
    }

    #pragma unroll
    for (int nc = 0; nc < 8; nc++) {
        const int col = 8*nc + 2*q;
        float bx = bo[col], by = bo[col + 1];
        float v[4];
        v[0] = acc[nc][0] + bx; v[1] = acc[nc][1] + by;
        v[2] = acc[nc][2] + bx; v[3] = acc[nc][3] + by;
        #pragma unroll
        for (int j = 0; j < 4; j++)
            v[j] = 0.5f * v[j] * (1.0f + erff(v[j] * 0.70710678118654752f));
        float2 oa; oa.x = v[0]; oa.y = v[1];
        float2 ob; ob.x = v[2]; ob.y = v[3];
        *(float2*)&out[(size_t)(m0 + rA)*Cdim + col]     = oa;
        *(float2*)&out[(size_t)(m0 + rA + 8)*Cdim + col] = ob;
    }
}

// ===========================================================================
extern "C" void kernel_launch(void* const* d_in, const int* in_sizes, int n_in,
                              void* d_out, int out_size)
{
    const float* X  = (const float*)d_in[0];   // hidden_states [4,2048,64]
    const float* Wq = (const float*)d_in[1];   // qkv_w [64,3072]
    const float* bq = (const float*)d_in[2];   // qkv_b [3072]
    const float* Wo = (const float*)d_in[3];   // out_w [1024,64]
    const float* bo = (const float*)d_in[4];   // out_b [64]
    float* out = (float*)d_out;

    cudaFuncSetAttribute(attn_kernel,
                         cudaFuncAttributeMaxDynamicSharedMemorySize,
                         SM_ATTN_BYTES);

    wconv_kernel<<<64, 1024>>>(Wo);
    qkv_kernel<<<dim3(48, 64), 256>>>(X, Wq, bq);
    attn_kernel<<<dim3(Nseq/128, Bsz*Hn), 256, SM_ATTN_BYTES>>>();
    out_kernel<<<MTOT/64, 128>>>(bo, out);
}

// round 6
// speedup vs baseline: 6.5458x; 1.0199x over previous
#include <cuda_runtime.h>
#include <cuda_fp16.h>
#include <math.h>
#include <stdint.h>

#define Bsz  4
#define Nseq 2048
#define Cdim 64
#define Hn   16
#define Dh   64
#define HID  1024
#define MTOT (Bsz*Nseq)     // 8192
#define QSC 0.18033688011112042f            /* 0.125 * log2(e) */

// Scratch (device globals)
__device__ __half g_qh[(size_t)Bsz*Hn*Nseq*Dh];   // [bh][n][d], pre-scaled
__device__ __half g_kh[(size_t)Bsz*Hn*Nseq*Dh];   // [bh][n][d]
__device__ __half g_vt[(size_t)Bsz*Hn*Dh*Nseq];   // [bh][d][n]  (V transposed)
__device__ __half g_ctxh[(size_t)MTOT*HID];       // [n][1024] half
__device__ __half g_woh[(size_t)Cdim*HID];        // [n=64][k=1024] (Wo^T, half)

__device__ __forceinline__ float ex2f(float x) {
    float r; asm("ex2.approx.ftz.f32 %0, %1;" : "=f"(r) : "f"(x)); return r;
}
__device__ __forceinline__ uint32_t ex2h2(uint32_t x) {
    uint32_t r; asm("ex2.approx.f16x2 %0, %1;" : "=r"(r) : "r"(x)); return r;
}
__device__ __forceinline__ uint32_t h2u(__half2 h) { return *(uint32_t*)&h; }
__device__ __forceinline__ __half2 u2h(uint32_t u) { return *(__half2*)&u; }

__device__ __forceinline__ void mma_f16(float d[4], const uint32_t a[4],
                                        uint32_t b0, uint32_t b1) {
    asm volatile("mma.sync.aligned.m16n8k16.row.col.f32.f16.f16.f32 "
        "{%0,%1,%2,%3}, {%4,%5,%6,%7}, {%8,%9}, {%0,%1,%2,%3};"
        : "+f"(d[0]), "+f"(d[1]), "+f"(d[2]), "+f"(d[3])
        : "r"(a[0]), "r"(a[1]), "r"(a[2]), "r"(a[3]), "r"(b0), "r"(b1));
}
__device__ __forceinline__ void cp16(uint32_t dst, const void* src) {
    asm volatile("cp.async.cg.shared.global [%0], [%1], 16;" :: "r"(dst), "l"(src));
}
__device__ __forceinline__ void cp_commit() {
    asm volatile("cp.async.commit_group;");
}
__device__ __forceinline__ void cp_wait0() {
    asm volatile("cp.async.wait_group 0;" ::: "memory");
}

// ===========================================================================
// Kernel 1: QKV projection via fp16 mma.
// ===========================================================================
#define XPAD 72
#define VTP 136
__global__ __launch_bounds__(256) void qkv_kernel(
    const float* __restrict__ X, const float* __restrict__ W,
    const float* __restrict__ bias)
{
    __shared__ __half Xh[128*XPAD];
    __shared__ __half Wh[64*XPAD];
    __shared__ __half VTs[64*VTP];
    const int m0 = blockIdx.y * 128;
    const int j0 = blockIdx.x * 64;
    const int tid = threadIdx.x;
    const int w = tid >> 5, lane = tid & 31;
    const int q = lane & 3, g = lane >> 2;

    #pragma unroll
    for (int it = 0; it < 8; it++) {
        int idx = tid + it*256;
        int r = idx >> 4, c = (idx & 15) * 4;
        float4 v = ((const float4*)(X + (size_t)m0*Cdim))[idx];
        uint2 p;
        p.x = h2u(__floats2half2_rn(v.x, v.y));
        p.y = h2u(__floats2half2_rn(v.z, v.w));
        *(uint2*)&Xh[r*XPAD + c] = p;
    }
    {
        const int n = tid & 63, kb = (tid >> 6) * 16;
        float v[16];
        #pragma unroll
        for (int k = 0; k < 16; k++)
            v[k] = W[(size_t)(kb + k)*(3*HID) + j0 + n];
        #pragma unroll
        for (int k = 0; k < 16; k += 2)
            *(uint32_t*)&Wh[n*XPAD + kb + k] = h2u(__floats2half2_rn(v[k], v[k+1]));
    }
    __syncthreads();

    const int rA = 16*w + g;
    uint32_t a[4][4];
    #pragma unroll
    for (int ks = 0; ks < 4; ks++) {
        a[ks][0] = *(uint32_t*)&Xh[rA*XPAD + 16*ks + 2*q];
        a[ks][1] = *(uint32_t*)&Xh[(rA+8)*XPAD + 16*ks + 2*q];
        a[ks][2] = *(uint32_t*)&Xh[rA*XPAD + 16*ks + 8 + 2*q];
        a[ks][3] = *(uint32_t*)&Xh[(rA+8)*XPAD + 16*ks + 8 + 2*q];
    }

    const int three = j0 / HID;          // uniform per block
    const int h     = (j0 >> 6) & 15;
    const int bb = m0 >> 11, n0 = m0 & 2047;
    const int nA = n0 + rA, nB = n0 + rA + 8;

    #pragma unroll
    for (int nc = 0; nc < 8; nc++) {
        float d[4] = {0.f, 0.f, 0.f, 0.f};
        #pragma unroll
        for (int ks = 0; ks < 4; ks++) {
            uint32_t b0 = *(uint32_t*)&Wh[(8*nc + g)*XPAD + 16*ks + 2*q];
            uint32_t b1 = *(uint32_t*)&Wh[(8*nc + g)*XPAD + 16*ks + 8 + 2*q];
            mma_f16(d, a[ks], b0, b1);
        }
        const int col = 8*nc + 2*q;
        float bx = bias[j0 + col], by = bias[j0 + col + 1];
        float v0 = d[0] + bx, v1 = d[1] + by;
        float v2 = d[2] + bx, v3 = d[3] + by;
        if (three == 0) {
            v0 *= QSC; v1 *= QSC; v2 *= QSC; v3 *= QSC;
            *(uint32_t*)&g_qh[((size_t)(bb*Hn + h)*Nseq + nA)*Dh + col] =
                h2u(__floats2half2_rn(v0, v1));
            *(uint32_t*)&g_qh[((size_t)(bb*Hn + h)*Nseq + nB)*Dh + col] =
                h2u(__floats2half2_rn(v2, v3));
        } else if (three == 1) {
            *(uint32_t*)&g_kh[((size_t)(bb*Hn + h)*Nseq + nA)*Dh + col] =
                h2u(__floats2half2_rn(v0, v1));
            *(uint32_t*)&g_kh[((size_t)(bb*Hn + h)*Nseq + nB)*Dh + col] =
                h2u(__floats2half2_rn(v2, v3));
        } else {
            VTs[(col    )*VTP + rA]     = __float2half_rn(v0);
            VTs[(col + 1)*VTP + rA]     = __float2half_rn(v1);
            VTs[(col    )*VTP + rA + 8] = __float2half_rn(v2);
            VTs[(col + 1)*VTP + rA + 8] = __float2half_rn(v3);
        }
    }

    if (three == 2) {
        __syncthreads();
        size_t base = (size_t)(bb*Hn + h)*Dh;
        #pragma unroll
        for (int it = 0; it < 4; it++) {
            int idx = tid + it*256;
            int d = idx >> 4, c = (idx & 15) * 8;
            *(uint4*)&g_vt[(base + d)*Nseq + n0 + c] = *(uint4*)&VTs[d*VTP + c];
        }
    }
}

// ===========================================================================
// Kernel 2: fp16 flash attention, cp.async double-buffered.
// L computed by fp32 summation of fp16 P fragments (off the tensor pipe).
// smem per buffer: Ks [128][72], Vt [64][136]
// ===========================================================================
#define KPADH 72
#define VPADH 136
#define KS_HALVES (128*KPADH)                 // 9216
#define VT_HALVES (64*VPADH)                  // 8704
#define BUF_HALVES (KS_HALVES + VT_HALVES)    // 17920
#define SM_ATTN_BYTES (2*BUF_HALVES*2)        // 71680 B

__global__ __launch_bounds__(256) void attn_kernel()
{
    extern __shared__ __half smh[];
    const uint32_t smbase = (uint32_t)__cvta_generic_to_shared(smh);

    const int tid = threadIdx.x;
    const int w = tid >> 5, lane = tid & 31;
    const int q = lane & 3, gg = lane >> 2;
    const int bh = blockIdx.y;
    const int q0 = blockIdx.x * 128;

    const __half* Kg  = g_kh + (size_t)bh*Nseq*Dh;
    const __half* Vtg = g_vt + (size_t)bh*Dh*Nseq;

    // ---- stage Q tile (buf0 Ks area), extract a-frags ----
    {
        const __half* Qg = g_qh + ((size_t)bh*Nseq + q0)*Dh;
        #pragma unroll
        for (int it = 0; it < 4; it++) {
            int idx = tid + it*256;
            int r = idx >> 3, c = (idx & 7) * 8;
            *(uint4*)&smh[r*KPADH + c] = ((const uint4*)Qg)[idx];
        }
    }
    __syncthreads();
    const int rA = 16*w + gg;
    uint32_t qa[4][4];
    #pragma unroll
    for (int ks = 0; ks < 4; ks++) {
        qa[ks][0] = *(uint32_t*)&smh[rA*KPADH + 16*ks + 2*q];
        qa[ks][1] = *(uint32_t*)&smh[(rA+8)*KPADH + 16*ks + 2*q];
        qa[ks][2] = *(uint32_t*)&smh[rA*KPADH + 16*ks + 8 + 2*q];
        qa[ks][3] = *(uint32_t*)&smh[(rA+8)*KPADH + 16*ks + 8 + 2*q];
    }
    __syncthreads();

    // ---- prologue: issue tile 0 into buf 0 ----
    {
        uint32_t ksb = smbase;
        uint32_t vtb = smbase + KS_HALVES*2;
        #pragma unroll
        for (int it = 0; it < 4; it++) {
            int idx = tid + it*256;
            int r = idx >> 3, c = (idx & 7) * 8;
            cp16(ksb + (r*KPADH + c)*2, Kg + idx*8);
        }
        #pragma unroll
        for (int it = 0; it < 4; it++) {
            int idx = tid + it*256;
            int d = idx >> 4, c = (idx & 15) * 8;
            cp16(vtb + (d*VPADH + c)*2, Vtg + (size_t)d*Nseq + c);
        }
        cp_commit();
    }

    float M0 = -1e30f, M1 = -1e30f, L0 = 0.f, L1 = 0.f;
    float O[8][4];
    #pragma unroll
    for (int dc = 0; dc < 8; dc++)
        #pragma unroll
        for (int j = 0; j < 4; j++) O[dc][j] = 0.f;

    for (int kt = 0; kt < 16; kt++) {
        cp_wait0();
        __syncthreads();    // data visible + all warps done reading other buf
        const int buf = kt & 1;

        if (kt < 15) {
            const int nb = buf ^ 1;
            uint32_t ksb = smbase + (nb*BUF_HALVES)*2;
            uint32_t vtb = ksb + KS_HALVES*2;
            const __half* Kt = Kg + (size_t)(kt+1)*128*Dh;
            const __half* Vs = Vtg + (kt+1)*128;
            #pragma unroll
            for (int it = 0; it < 4; it++) {
                int idx = tid + it*256;
                int r = idx >> 3, c = (idx & 7) * 8;
                cp16(ksb + (r*KPADH + c)*2, Kt + idx*8);
            }
            #pragma unroll
            for (int it = 0; it < 4; it++) {
                int idx = tid + it*256;
                int d = idx >> 4, c = (idx & 15) * 8;
                cp16(vtb + (d*VPADH + c)*2, Vs + (size_t)d*Nseq + c);
            }
            cp_commit();
        }

        const __half* Ks = smh + buf*BUF_HALVES;
        const __half* Vt = Ks + KS_HALVES;

        // ---- S = Q K^T ----
        float s[16][4];
        #pragma unroll
        for (int c = 0; c < 16; c++) {
            s[c][0] = 0.f; s[c][1] = 0.f; s[c][2] = 0.f; s[c][3] = 0.f;
            #pragma unroll
            for (int ks = 0; ks < 4; ks++) {
                uint32_t b0 = *(uint32_t*)&Ks[(8*c + gg)*KPADH + 16*ks + 2*q];
                uint32_t b1 = *(uint32_t*)&Ks[(8*c + gg)*KPADH + 16*ks + 8 + 2*q];
                mma_f16(s[c], qa[ks], b0, b1);
            }
        }

        // ---- row max (quad reduction), rescale ----
        float m0 = s[0][0], m1 = s[0][2];
        #pragma unroll
        for (int c = 0; c < 16; c++) {
            m0 = fmaxf(m0, fmaxf(s[c][0], s[c][1]));
            m1 = fmaxf(m1, fmaxf(s[c][2], s[c][3]));
        }
        m0 = fmaxf(m0, __shfl_xor_sync(0xffffffffu, m0, 1));
        m0 = fmaxf(m0, __shfl_xor_sync(0xffffffffu, m0, 2));
        m1 = fmaxf(m1, __shfl_xor_sync(0xffffffffu, m1, 1));
        m1 = fmaxf(m1, __shfl_xor_sync(0xffffffffu, m1, 2));
        float mn0 = fmaxf(M0, m0), mn1 = fmaxf(M1, m1);
        float al0 = ex2f(M0 - mn0), al1 = ex2f(M1 - mn1);
        M0 = mn0; M1 = mn1;

        #pragma unroll
        for (int dc = 0; dc < 8; dc++) {
            O[dc][0] *= al0; O[dc][1] *= al0;
            O[dc][2] *= al1; O[dc][3] *= al1;
        }

        // ---- P = exp2(s - m) in f16x2 (A-fragment layout) ----
        uint32_t pa[8][4];
        #pragma unroll
        for (int kc = 0; kc < 8; kc++) {
            pa[kc][0] = ex2h2(h2u(__floats2half2_rn(s[2*kc][0]-mn0,   s[2*kc][1]-mn0)));
            pa[kc][1] = ex2h2(h2u(__floats2half2_rn(s[2*kc][2]-mn1,   s[2*kc][3]-mn1)));
            pa[kc][2] = ex2h2(h2u(__floats2half2_rn(s[2*kc+1][0]-mn0, s[2*kc+1][1]-mn0)));
            pa[kc][3] = ex2h2(h2u(__floats2half2_rn(s[2*kc+1][2]-mn1, s[2*kc+1][3]-mn1)));
        }

        // ---- L += sum(P) in fp32 (fma/alu pipe, not tensor) ----
        {
            float sA = 0.f, sB = 0.f;
            #pragma unroll
            for (int kc = 0; kc < 8; kc++) {
                float2 f0 = __half22float2(u2h(pa[kc][0]));
                float2 f2 = __half22float2(u2h(pa[kc][2]));
                sA += (f0.x + f0.y) + (f2.x + f2.y);
                float2 f1 = __half22float2(u2h(pa[kc][1]));
                float2 f3 = __half22float2(u2h(pa[kc][3]));
                sB += (f1.x + f1.y) + (f3.x + f3.y);
            }
            sA += __shfl_xor_sync(0xffffffffu, sA, 1);
            sA += __shfl_xor_sync(0xffffffffu, sA, 2);
            sB += __shfl_xor_sync(0xffffffffu, sB, 1);
            sB += __shfl_xor_sync(0xffffffffu, sB, 2);
            L0 = L0*al0 + sA;
            L1 = L1*al1 + sB;
        }

        // ---- O += P V ----
        #pragma unroll
        for (int kc = 0; kc < 8; kc++) {
            #pragma unroll
            for (int dc = 0; dc < 8; dc++) {
                uint32_t b0 = *(uint32_t*)&Vt[(8*dc + gg)*VPADH + 16*kc + 2*q];
                uint32_t b1 = *(uint32_t*)&Vt[(8*dc + gg)*VPADH + 16*kc + 8 + 2*q];
                mma_f16(O[dc], pa[kc], b0, b1);
            }
        }
    }

    const float i0 = 1.f / L0, i1 = 1.f / L1;
    const int bb = bh >> 4, h = bh & 15;
    const int r0 = q0 + rA;
    #pragma unroll
    for (int dc = 0; dc < 8; dc++) {
        uint32_t pa0 = h2u(__floats2half2_rn(O[dc][0]*i0, O[dc][1]*i0));
        uint32_t pb0 = h2u(__floats2half2_rn(O[dc][2]*i1, O[dc][3]*i1));
        *(uint32_t*)&g_ctxh[(size_t)(bb*Nseq + r0)*HID     + h*64 + 8*dc + 2*q] = pa0;
        *(uint32_t*)&g_ctxh[(size_t)(bb*Nseq + r0 + 8)*HID + h*64 + 8*dc + 2*q] = pb0;
    }
}

// ===========================================================================
// Kernel 3a: convert Wo -> half transposed g_woh[n][k]
// ===========================================================================
__global__ void wconv_kernel(const float* __restrict__ Wo) {
    int idx = blockIdx.x * 1024 + threadIdx.x;
    int n = idx >> 10, k = idx & 1023;
    g_woh[idx] = __float2half_rn(Wo[(size_t)k*Cdim + n]);
}

// ===========================================================================
// Kernel 3b: out = GELU(ctx @ Wo + bo) via fp16 mma.
// grid=128: CTA = 64 rows. 256 threads, 8 warps: warp (w&3) -> 16-row group,
// (w>>2) -> n-half. Double-buffered cp.async over 16 k-tiles of 64.
// ===========================================================================
#define OPAD 72
__global__ __launch_bounds__(256) void out_kernel(
    const float* __restrict__ bo, float* __restrict__ out)
{
    __shared__ __half As[2][64*OPAD];
    __shared__ __half Bs[2][64*OPAD];
    const int m0 = blockIdx.x * 64;
    const int tid = threadIdx.x;
    const int w = tid >> 5, lane = tid & 31;
    const int q = lane & 3, g = lane >> 2;
    const int rA = 16*(w & 3) + g;
    const int nh = w >> 2;                    // n-half: cols [32nh, 32nh+32)

    const uint32_t asb = (uint32_t)__cvta_generic_to_shared(&As[0][0]);
    const uint32_t bsb = (uint32_t)__cvta_generic_to_shared(&Bs[0][0]);

    // prologue: tile 0
    #pragma unroll
    for (int it = 0; it < 2; it++) {
        int idx = tid + it*256;
        int r = idx >> 3, c = (idx & 7) * 8;
        cp16(asb + (r*OPAD + c)*2, &g_ctxh[(size_t)(m0 + r)*HID + c]);
        cp16(bsb + (r*OPAD + c)*2, &g_woh[(size_t)r*HID + c]);
    }
    cp_commit();

    float acc[4][4];
    #pragma unroll
    for (int nc = 0; nc < 4; nc++)
        #pragma unroll
        for (int j = 0; j < 4; j++) acc[nc][j] = 0.f;

    for (int kt = 0; kt < 16; kt++) {
        cp_wait0();
        __syncthreads();
        const int buf = kt & 1;

        if (kt < 15) {
            const int nb = buf ^ 1;
            #pragma unroll
            for (int it = 0; it < 2; it++) {
                int idx = tid + it*256;
                int r = idx >> 3, c = (idx & 7) * 8;
                cp16(asb + (nb*64*OPAD + r*OPAD + c)*2,
                     &g_ctxh[(size_t)(m0 + r)*HID + (kt+1)*64 + c]);
                cp16(bsb + (nb*64*OPAD + r*OPAD + c)*2,
                     &g_woh[(size_t)r*HID + (kt+1)*64 + c]);
            }
            cp_commit();
        }

        uint32_t a[4][4];
        #pragma unroll
        for (int ks = 0; ks < 4; ks++) {
            a[ks][0] = *(uint32_t*)&As[buf][rA*OPAD + 16*ks + 2*q];
            a[ks][1] = *(uint32_t*)&As[buf][(rA+8)*OPAD + 16*ks + 2*q];
            a[ks][2] = *(uint32_t*)&As[buf][rA*OPAD + 16*ks + 8 + 2*q];
            a[ks][3] = *(uint32_t*)&As[buf][(rA+8)*OPAD + 16*ks + 8 + 2*q];
        }
        #pragma unroll
        for (int nc = 0; nc < 4; nc++) {
            const int n8 = 4*nh + nc;
            #pragma unroll
            for (int ks = 0; ks < 4; ks++) {
                uint32_t b0 = *(uint32_t*)&Bs[buf][(8*n8 + g)*OPAD + 16*ks + 2*q];
                uint32_t b1 = *(uint32_t*)&Bs[buf][(8*n8 + g)*OPAD + 16*ks + 8 + 2*q];
                mma_f16(acc[nc], a[ks], b0, b1);
            }
        }
    }

    #pragma unroll
    for (int nc = 0; nc < 4; nc++) {
        const int col = 8*(4*nh + nc) + 2*q;
        float bx = bo[col], by = bo[col + 1];
        float v[4];
        v[0] = acc[nc][0] + bx; v[1] = acc[nc][1] + by;
        v[2] = acc[nc][2] + bx; v[3] = acc[nc][3] + by;
        #pragma unroll
        for (int j = 0; j < 4; j++)
            v[j] = 0.5f * v[j] * (1.0f + erff(v[j] * 0.70710678118654752f));
        float2 oa; oa.x = v[0]; oa.y = v[1];
        float2 ob; ob.x = v[2]; ob.y = v[3];
        *(float2*)&out[(size_t)(m0 + rA)*Cdim + col]     = oa;
        *(float2*)&out[(size_t)(m0 + rA + 8)*Cdim + col] = ob;
    }
}

// ===========================================================================
extern "C" void kernel_launch(void* const* d_in, const int* in_sizes, int n_in,
                              void* d_out, int out_size)
{
    const float* X  = (const float*)d_in[0];   // hidden_states [4,2048,64]
    const float* Wq = (const float*)d_in[1];   // qkv_w [64,3072]
    const float* bq = (const float*)d_in[2];   // qkv_b [3072]
    const float* Wo = (const float*)d_in[3];   // out_w [1024,64]
    const float* bo = (const float*)d_in[4];   // out_b [64]
    float* out = (float*)d_out;

    cudaFuncSetAttribute(attn_kernel,
                         cudaFuncAttributeMaxDynamicSharedMemorySize,
                         SM_ATTN_BYTES);

    wconv_kernel<<<64, 1024>>>(Wo);
    qkv_kernel<<<dim3(48, 64), 256>>>(X, Wq, bq);
    attn_kernel<<<dim3(Nseq/128, Bsz*Hn), 256, SM_ATTN_BYTES>>>();
    out_kernel<<<MTOT/64, 256>>>(bo, out);
}